// round 7
// baseline (speedup 1.0000x reference)
#include <cuda_runtime.h>
#include <cuda_bf16.h>
#include <mma.h>
#include <math.h>

using namespace nvcuda;

#define TT 512
#define BB 256
#define IND 256
#define HH 512
#define OUTD 64
#define NBLK 128
#define WSTR 1544
#define ASTR 72

// ---------------- device scratch (static allocations only) ----------------
__device__ __nv_bfloat16 g_Xs[(size_t)TT*BB*512];   // per row: [xhi(256) | xlo(256)]
// Split-bf16 activations, per row layout: [hi(512) | lo(512)]
__device__ __nv_bfloat16 g_Are[BB*1024];
__device__ __nv_bfloat16 g_Aim[BB*1024];
__device__ __nv_bfloat16 g_Amod[BB*1024];
__device__ float g_zre[BB*HH];
__device__ float g_zim[BB*HH];
__device__ float g_gre[BB*HH];
__device__ float g_gim[BB*HH];
__device__ float g_gtau[BB*HH];
__device__ float g_gux[BB*HH];
__device__ float g_bias_re[HH];
__device__ float g_bias_im[HH];
__device__ float g_partials[NBLK];
__device__ int bar_cnt;
__device__ volatile unsigned bar_gen;

__device__ __forceinline__ float sigf(float v) { return 1.0f / (1.0f + expf(-v)); }

__device__ __forceinline__ float clampf(float v, float lo, float hi) {
    return fminf(hi, fmaxf(lo, v));
}

// Software grid barrier: all NBLK blocks resident (128 under 148 SMs, 1 CTA/SM).
__device__ __forceinline__ void grid_barrier() {
    __syncthreads();
    if (threadIdx.x == 0) {
        unsigned g = bar_gen;
        __threadfence();
        if (atomicAdd(&bar_cnt, 1) == NBLK - 1) {
            bar_cnt = 0;
            __threadfence();
            bar_gen = g + 1;
        } else {
            while (bar_gen == g) { }
        }
        __threadfence();
    }
    __syncthreads();
}

__global__ void __launch_bounds__(256, 1)
twistor_persistent(const float* __restrict__ x,
                   const float* __restrict__ W_real_w, const float* __restrict__ W_real_b,
                   const float* __restrict__ W_imag_w, const float* __restrict__ W_imag_b,
                   const float* __restrict__ U_w,      const float* __restrict__ U_b,
                   const float* __restrict__ W_tau_w,  const float* __restrict__ W_tau_b,
                   const float* __restrict__ mask_real,const float* __restrict__ mask_imag,
                   const float* __restrict__ tau_bias,
                   const float* __restrict__ b_real,   const float* __restrict__ b_imag,
                   const float* __restrict__ out_w,    const float* __restrict__ out_b,
                   float* __restrict__ y)
{
    extern __shared__ __align__(16) char dsmem[];
    __nv_bfloat16* sW  = (__nv_bfloat16*)dsmem;          // 32 rows x WSTR
    __nv_bfloat16* sA0 = sW + 32*WSTR;                   // 128 rows x ASTR
    __nv_bfloat16* sA1 = sA0 + 128*ASTR;

    __shared__ float zsm[2][512];
    __shared__ float red[4][2][64];
    __shared__ float rbuf[8];
    __shared__ float warp_s[4];

    int tid = threadIdx.x;
    int bx  = blockIdx.x;
    int gtid = bx*256 + tid;
    const int NTOT = NBLK*256;

    // ---------------- tile mapping ---------------------------------------
    int which = bx >> 5;          // 0:re 1:im 2:tau 3:Ux
    int tile  = bx & 31;
    int mi    = tile >> 4;        // 0..1
    int ni    = tile & 15;        // 0..15
    int m0    = mi * 128;
    int n0    = ni * 32;

    // ---------------- prologue ------------------------------------------
    // Build this block's weight slice (rows n0..n0+31) directly into smem,
    // stacked split layout along k: [hi | lo | hi] (heavy) or [hi | lo | hi] (Ux).
    if (which < 3) {
        for (int idx = tid; idx < 32*512; idx += 256) {
            int r = idx >> 9;
            int c = idx & 511;
            int grow = n0 + r;
            float wv;
            if (which == 0) {
                wv = W_real_w[grow*512 + c] * sigf(mask_real[grow*512 + c]);
            } else if (which == 1) {
                wv = W_imag_w[grow*512 + c] * sigf(mask_imag[grow*512 + c]);
            } else {
                wv = W_tau_w[grow*512 + c];
            }
            __nv_bfloat16 hb = __float2bfloat16_rn(wv);
            float hv = __bfloat162float(hb);
            __nv_bfloat16 lb = __float2bfloat16_rn(wv - hv);
            sW[r*WSTR + c]        = hb;
            sW[r*WSTR + 512 + c]  = lb;
            sW[r*WSTR + 1024 + c] = hb;
        }
    } else {
        for (int idx = tid; idx < 32*256; idx += 256) {
            int r = idx >> 8;
            int c = idx & 255;
            float wv = U_w[(n0 + r)*256 + c];
            __nv_bfloat16 hb = __float2bfloat16_rn(wv);
            float hv = __bfloat162float(hb);
            __nv_bfloat16 lb = __float2bfloat16_rn(wv - hv);
            sW[r*WSTR + c]       = hb;
            sW[r*WSTR + 256 + c] = lb;
            sW[r*WSTR + 512 + c] = hb;
        }
    }
    // x split for all timesteps (grid-strided, all blocks cooperate)
    for (size_t i = gtid; i < (size_t)TT*BB*IND; i += NTOT) {
        size_t rr = i >> 8;
        int cc = (int)(i & 255);
        float wv = x[i];
        __nv_bfloat16 hb = __float2bfloat16_rn(wv);
        float hv = __bfloat162float(hb);
        __nv_bfloat16 lb = __float2bfloat16_rn(wv - hv);
        g_Xs[rr*512 + cc] = hb;
        g_Xs[rr*512 + 256 + cc] = lb;
    }
    // state init
    {
        __nv_bfloat16 mh = __float2bfloat16_rn(1e-6f);
        float mhv = __bfloat162float(mh);
        __nv_bfloat16 ml = __float2bfloat16_rn(1e-6f - mhv);
        __nv_bfloat16 zb = __float2bfloat16_rn(0.0f);
        for (int i = gtid; i < BB*HH; i += NTOT) {
            int rr = i >> 9;
            int cc = i & 511;
            g_zre[i] = 0.0f;
            g_zim[i] = 0.0f;
            g_Are[rr*1024+cc] = zb;
            g_Are[rr*1024+512+cc] = zb;
            g_Aim[rr*1024+cc] = zb;
            g_Aim[rr*1024+512+cc] = zb;
            g_Amod[rr*1024+cc] = mh;
            g_Amod[rr*1024+512+cc] = ml;
        }
    }
    for (int i = gtid; i < HH; i += NTOT) {
        g_bias_re[i] = W_real_b[i] + U_b[i] + b_real[i];
        g_bias_im[i] = W_imag_b[i] + U_b[i] + b_imag[i];
    }
    grid_barrier();

    const __nv_bfloat16* Abase;
    float* C;
    int KP;
    int RSA;
    if (which == 0) {
        Abase = g_Are;  C = g_gre;  KP = 1536; RSA = 1024;
    } else if (which == 1) {
        Abase = g_Aim;  C = g_gim;  KP = 1536; RSA = 1024;
    } else if (which == 2) {
        Abase = g_Amod; C = g_gtau; KP = 1536; RSA = 1024;
    } else {
        Abase = g_Xs;   C = g_gux;  KP = 768;  RSA = 512;
    }
    int NC = KP >> 6;

    int arow = tid >> 1;            // 0..127
    int acol = (tid & 1) * 32;      // element offset of this thread's 32-el half
    int wm   = tid >> 5;            // warp id 0..7 -> rows wm*16

    for (int t = 0; t < TT; t++) {
        // ================= phase A: split-bf16 wmma GEMM ===================
        {
            const __nv_bfloat16* Ag = Abase;
            if (which == 3) {
                Ag = g_Xs + (size_t)t*BB*512;
            }

            wmma::fragment<wmma::accumulator, 16, 16, 16, float> acc0;
            wmma::fragment<wmma::accumulator, 16, 16, 16, float> acc1;
            wmma::fill_fragment(acc0, 0.0f);
            wmma::fill_fragment(acc1, 0.0f);

            // chunk 0 load
            uint4 r0 = *(const uint4*)(Ag + (size_t)(m0+arow)*RSA + acol);
            uint4 r1 = *(const uint4*)(Ag + (size_t)(m0+arow)*RSA + acol + 8);
            uint4 r2 = *(const uint4*)(Ag + (size_t)(m0+arow)*RSA + acol + 16);
            uint4 r3 = *(const uint4*)(Ag + (size_t)(m0+arow)*RSA + acol + 24);
            *(uint4*)(sA0 + arow*ASTR + acol)      = r0;
            *(uint4*)(sA0 + arow*ASTR + acol + 8)  = r1;
            *(uint4*)(sA0 + arow*ASTR + acol + 16) = r2;
            *(uint4*)(sA0 + arow*ASTR + acol + 24) = r3;
            __syncthreads();

            for (int ch = 0; ch < NC; ch++) {
                const __nv_bfloat16* sAc = (ch & 1) ? sA1 : sA0;
                __nv_bfloat16* sAn = (ch & 1) ? sA0 : sA1;
                if (ch + 1 < NC) {
                    int kc = (ch + 1) << 6;
                    int ac;
                    if (which == 3) {
                        if (kc < 512) { ac = kc & 255; } else { ac = kc - 256; }
                    } else {
                        if (kc < 1024) { ac = kc & 511; } else { ac = kc - 512; }
                    }
                    r0 = *(const uint4*)(Ag + (size_t)(m0+arow)*RSA + ac + acol);
                    r1 = *(const uint4*)(Ag + (size_t)(m0+arow)*RSA + ac + acol + 8);
                    r2 = *(const uint4*)(Ag + (size_t)(m0+arow)*RSA + ac + acol + 16);
                    r3 = *(const uint4*)(Ag + (size_t)(m0+arow)*RSA + ac + acol + 24);
                }
                int kc0 = ch << 6;
                #pragma unroll
                for (int q = 0; q < 4; q++) {
                    wmma::fragment<wmma::matrix_a, 16, 16, 16, __nv_bfloat16, wmma::row_major> fa;
                    wmma::fragment<wmma::matrix_b, 16, 16, 16, __nv_bfloat16, wmma::col_major> fb0;
                    wmma::fragment<wmma::matrix_b, 16, 16, 16, __nv_bfloat16, wmma::col_major> fb1;
                    wmma::load_matrix_sync(fa,  sAc + (wm*16)*ASTR + q*16, ASTR);
                    wmma::load_matrix_sync(fb0, sW + kc0 + q*16, WSTR);
                    wmma::load_matrix_sync(fb1, sW + 16*WSTR + kc0 + q*16, WSTR);
                    wmma::mma_sync(acc0, fa, fb0, acc0);
                    wmma::mma_sync(acc1, fa, fb1, acc1);
                }
                if (ch + 1 < NC) {
                    *(uint4*)(sAn + arow*ASTR + acol)      = r0;
                    *(uint4*)(sAn + arow*ASTR + acol + 8)  = r1;
                    *(uint4*)(sAn + arow*ASTR + acol + 16) = r2;
                    *(uint4*)(sAn + arow*ASTR + acol + 24) = r3;
                    __syncthreads();
                }
            }

            float* Cout = C + (size_t)(m0 + wm*16)*512 + n0;
            wmma::store_matrix_sync(Cout,      acc0, 512, wmma::mem_row_major);
            wmma::store_matrix_sync(Cout + 16, acc1, 512, wmma::mem_row_major);
        }
        grid_barrier();

        // ================= phase B1: elementwise + partial sums =============
        float dre[4];
        float dimm[4];
        float zreL[4];
        float zimL[4];
        {
            int i4 = bx * 256 + tid;
            float4 vre = ((const float4*)g_gre)[i4];
            float4 vim = ((const float4*)g_gim)[i4];
            float4 vta = ((const float4*)g_gtau)[i4];
            float4 vux = ((const float4*)g_gux)[i4];
            float4 vzr = ((const float4*)g_zre)[i4];
            float4 vzi = ((const float4*)g_zim)[i4];
            int h0 = (i4 & 127) * 4;
            float4 vbr  = *(const float4*)(&g_bias_re[h0]);
            float4 vbi  = *(const float4*)(&g_bias_im[h0]);
            float4 vwtb = *(const float4*)(&W_tau_b[h0]);
            float4 vtb  = *(const float4*)(&tau_bias[h0]);

            float tre[4];
            float tim[4];
            float tta[4];
            float tux[4];
            float tzr[4];
            float tzi[4];
            float tbr[4];
            float tbi[4];
            float twtb[4];
            float ttb[4];
            tre[0] = vre.x; tre[1] = vre.y; tre[2] = vre.z; tre[3] = vre.w;
            tim[0] = vim.x; tim[1] = vim.y; tim[2] = vim.z; tim[3] = vim.w;
            tta[0] = vta.x; tta[1] = vta.y; tta[2] = vta.z; tta[3] = vta.w;
            tux[0] = vux.x; tux[1] = vux.y; tux[2] = vux.z; tux[3] = vux.w;
            tzr[0] = vzr.x; tzr[1] = vzr.y; tzr[2] = vzr.z; tzr[3] = vzr.w;
            tzi[0] = vzi.x; tzi[1] = vzi.y; tzi[2] = vzi.z; tzi[3] = vzi.w;
            tbr[0] = vbr.x; tbr[1] = vbr.y; tbr[2] = vbr.z; tbr[3] = vbr.w;
            tbi[0] = vbi.x; tbi[1] = vbi.y; tbi[2] = vbi.z; tbi[3] = vbi.w;
            twtb[0] = vwtb.x; twtb[1] = vwtb.y; twtb[2] = vwtb.z; twtb[3] = vwtb.w;
            ttb[0] = vtb.x; ttb[1] = vtb.y; ttb[2] = vtb.z; ttb[3] = vtb.w;

            float lsum = 0.0f;
            #pragma unroll
            for (int j = 0; j < 4; j++) {
                float dzr = tre[j] + tux[j] + tbr[j] - tzr[j];
                float dzi = tim[j] + tux[j] + tbi[j] - tzi[j];
                float tau = clampf(sigf(tta[j] + twtb[j]) + ttb[j], 0.01f, 1.0f) + 1e-6f;
                float dr  = clampf(dzr / tau, -10.0f, 10.0f);
                float di  = clampf(dzi / tau, -10.0f, 10.0f);
                lsum += sqrtf(dr*dr + di*di + 1e-12f);
                dre[j] = dr;
                dimm[j] = di;
                zreL[j] = tzr[j];
                zimL[j] = tzi[j];
            }
            #pragma unroll
            for (int off = 16; off > 0; off >>= 1) {
                lsum += __shfl_down_sync(0xFFFFFFFFu, lsum, off);
            }
            if ((tid & 31) == 0) {
                rbuf[tid >> 5] = lsum;
            }
            __syncthreads();
            if (tid == 0) {
                float s = 0.0f;
                #pragma unroll
                for (int ww = 0; ww < 8; ww++) {
                    s += rbuf[ww];
                }
                g_partials[bx] = s;
            }
        }
        grid_barrier();

        // ================= phase B2: scale + update + readout ===============
        {
            if (tid < 128) {
                float pv = g_partials[tid];
                #pragma unroll
                for (int off = 16; off > 0; off >>= 1) {
                    pv += __shfl_down_sync(0xFFFFFFFFu, pv, off);
                }
                if ((tid & 31) == 0) {
                    warp_s[tid >> 5] = pv;
                }
            }
            __syncthreads();
            float tot  = ((warp_s[0] + warp_s[1]) + warp_s[2]) + warp_s[3];
            float mean = tot / (float)(BB * HH);
            float scale = 1.0f;
            if (mean > 5.0f) {
                scale = 5.0f / (mean + 1e-6f);
            }

            int i4 = bx * 256 + tid;
            int flat0 = i4 * 4;
            int arw   = flat0 >> 9;
            int acl   = flat0 & 511;
            int abase = arw*1024 + acl;

            float zrA[4];
            float ziA[4];
            #pragma unroll
            for (int j = 0; j < 4; j++) {
                float znr = clampf(zreL[j] + 0.1f * scale * dre[j],  -100.0f, 100.0f);
                float zni = clampf(zimL[j] + 0.1f * scale * dimm[j], -100.0f, 100.0f);
                zrA[j] = znr;
                ziA[j] = zni;
                float arv = tanhf(znr);
                float aiv = tanhf(zni);
                float amv = sqrtf(znr*znr + zni*zni + 1e-12f);
                __nv_bfloat16 hb;
                float hv;
                hb = __float2bfloat16_rn(arv);
                hv = __bfloat162float(hb);
                g_Are[abase+j] = hb;
                g_Are[abase+512+j] = __float2bfloat16_rn(arv - hv);
                hb = __float2bfloat16_rn(aiv);
                hv = __bfloat162float(hb);
                g_Aim[abase+j] = hb;
                g_Aim[abase+512+j] = __float2bfloat16_rn(aiv - hv);
                hb = __float2bfloat16_rn(amv);
                hv = __bfloat162float(hb);
                g_Amod[abase+j] = hb;
                g_Amod[abase+512+j] = __float2bfloat16_rn(amv - hv);
            }
            float4 vout;
            vout = make_float4(zrA[0], zrA[1], zrA[2], zrA[3]);
            ((float4*)g_zre)[i4] = vout;
            ((float4*)(&zsm[0][0]))[tid] = vout;
            vout = make_float4(ziA[0], ziA[1], ziA[2], ziA[3]);
            ((float4*)g_zim)[i4] = vout;
            __syncthreads();

            // readout: y[t, 2bx + r, :] = zsm[r] times out_w transpose + out_b
            int o   = tid & 63;
            int seg = tid >> 6;
            float acc0 = 0.0f;
            float acc1 = 0.0f;
            const float4* wrow = (const float4*)(out_w + (size_t)o * 512 + seg * 128);
            #pragma unroll 8
            for (int k4 = 0; k4 < 32; k4++) {
                float4 wv = wrow[k4];
                float4 z0 = *(const float4*)(&zsm[0][seg*128 + k4*4]);
                float4 z1 = *(const float4*)(&zsm[1][seg*128 + k4*4]);
                acc0 += wv.x*z0.x + wv.y*z0.y + wv.z*z0.z + wv.w*z0.w;
                acc1 += wv.x*z1.x + wv.y*z1.y + wv.z*z1.z + wv.w*z1.w;
            }
            red[seg][0][o] = acc0;
            red[seg][1][o] = acc1;
            __syncthreads();
            if (seg == 0) {
                float ob = out_b[o];
                #pragma unroll
                for (int r = 0; r < 2; r++) {
                    float yv = red[0][r][o] + red[1][r][o] + red[2][r][o] + red[3][r][o] + ob;
                    y[((size_t)t * BB + bx*2 + r) * OUTD + o] = yv;
                }
            }
        }
        grid_barrier();
    }
}

// ---------------- host launcher (graph-capturable, single node) ------------
extern "C" void kernel_launch(void* const* d_in, const int* in_sizes, int n_in,
                              void* d_out, int out_size)
{
    const float* x         = (const float*)d_in[0];
    const float* W_real_w  = (const float*)d_in[1];
    const float* W_real_b  = (const float*)d_in[2];
    const float* W_imag_w  = (const float*)d_in[3];
    const float* W_imag_b  = (const float*)d_in[4];
    const float* U_w       = (const float*)d_in[5];
    const float* U_b       = (const float*)d_in[6];
    const float* W_tau_w   = (const float*)d_in[7];
    const float* W_tau_b   = (const float*)d_in[8];
    const float* mask_real = (const float*)d_in[9];
    const float* mask_imag = (const float*)d_in[10];
    const float* tau_bias  = (const float*)d_in[11];
    const float* b_real    = (const float*)d_in[12];
    const float* b_imag    = (const float*)d_in[13];
    const float* out_w     = (const float*)d_in[14];
    const float* out_b     = (const float*)d_in[15];
    float* y = (float*)d_out;

    int dyn_smem = (32*WSTR + 2*128*ASTR) * (int)sizeof(__nv_bfloat16);
    cudaFuncSetAttribute(twistor_persistent,
                         cudaFuncAttributeMaxDynamicSharedMemorySize, dyn_smem);
    twistor_persistent<<<NBLK, 256, dyn_smem>>>(x, W_real_w, W_real_b, W_imag_w, W_imag_b,
                                                U_w, U_b, W_tau_w, W_tau_b,
                                                mask_real, mask_imag, tau_bias,
                                                b_real, b_imag, out_w, out_b, y);
}

// round 8
// speedup vs baseline: 1.1412x; 1.1412x over previous
#include <cuda_runtime.h>
#include <cuda_bf16.h>
#include <mma.h>
#include <math.h>

using namespace nvcuda;

#define TT 512
#define BB 256
#define IND 256
#define HH 512
#define OUTD 64
#define NBLK 128
#define NTHR 512

// ---------------- device scratch (static allocations only) ----------------
// Stacked split-bf16 weights, per row layout: [hi(512) | lo(512) | hi(512)]
__device__ __nv_bfloat16 g_Wsre[HH*1536];
__device__ __nv_bfloat16 g_Wsim[HH*1536];
__device__ __nv_bfloat16 g_Wstau[HH*1536];
__device__ __nv_bfloat16 g_Us[HH*768];
__device__ __nv_bfloat16 g_Xs[(size_t)TT*BB*512];
// Split-bf16 activations, per row layout: [hi(512) | lo(512)]
__device__ __nv_bfloat16 g_Are[BB*1024];
__device__ __nv_bfloat16 g_Aim[BB*1024];
__device__ __nv_bfloat16 g_Amod[BB*1024];
__device__ float g_zre[BB*HH];
__device__ float g_zim[BB*HH];
__device__ float g_gre[BB*HH];
__device__ float g_gim[BB*HH];
__device__ float g_gtau[BB*HH];
__device__ float g_gux[BB*HH];
__device__ float g_bias_re[HH];
__device__ float g_bias_im[HH];
__device__ float g_partials[NBLK];
__device__ int bar_cnt;
__device__ volatile unsigned bar_gen;

__device__ __forceinline__ float sigf(float v) { return 1.0f / (1.0f + expf(-v)); }

__device__ __forceinline__ float clampf(float v, float lo, float hi) {
    return fminf(hi, fmaxf(lo, v));
}

// Software grid barrier: all NBLK blocks resident (128 under 148 SMs, 1 CTA/SM).
__device__ __forceinline__ void grid_barrier() {
    __syncthreads();
    if (threadIdx.x == 0) {
        unsigned g = bar_gen;
        __threadfence();
        if (atomicAdd(&bar_cnt, 1) == NBLK - 1) {
            bar_cnt = 0;
            __threadfence();
            bar_gen = g + 1;
        } else {
            while (bar_gen == g) { }
        }
        __threadfence();
    }
    __syncthreads();
}

__global__ void __launch_bounds__(NTHR, 1)
twistor_persistent(const float* __restrict__ x,
                   const float* __restrict__ W_real_w, const float* __restrict__ W_real_b,
                   const float* __restrict__ W_imag_w, const float* __restrict__ W_imag_b,
                   const float* __restrict__ U_w,      const float* __restrict__ U_b,
                   const float* __restrict__ W_tau_w,  const float* __restrict__ W_tau_b,
                   const float* __restrict__ mask_real,const float* __restrict__ mask_imag,
                   const float* __restrict__ tau_bias,
                   const float* __restrict__ b_real,   const float* __restrict__ b_imag,
                   const float* __restrict__ out_w,    const float* __restrict__ out_b,
                   float* __restrict__ y)
{
    __shared__ __nv_bfloat16 sA[2][64*72];
    __shared__ __nv_bfloat16 sB[2][64*72];
    __shared__ float zsm[2][512];
    __shared__ float red[8][2][64];
    __shared__ float rbuf[16];
    __shared__ float warp_s[4];

    int tid = threadIdx.x;
    int bx  = blockIdx.x;
    int gtid = bx*NTHR + tid;
    const int NTOT = NBLK*NTHR;

    // ---------------- prologue ------------------------------------------
    for (int i = gtid; i < HH*HH; i += NTOT) {
        int rr = i >> 9;
        int cc = i & 511;
        int base = rr*1536 + cc;
        float wv;
        float hv;
        __nv_bfloat16 hb;
        __nv_bfloat16 lb;
        wv = W_real_w[i] * sigf(mask_real[i]);
        hb = __float2bfloat16_rn(wv);
        hv = __bfloat162float(hb);
        lb = __float2bfloat16_rn(wv - hv);
        g_Wsre[base] = hb;
        g_Wsre[base+512] = lb;
        g_Wsre[base+1024] = hb;
        wv = W_imag_w[i] * sigf(mask_imag[i]);
        hb = __float2bfloat16_rn(wv);
        hv = __bfloat162float(hb);
        lb = __float2bfloat16_rn(wv - hv);
        g_Wsim[base] = hb;
        g_Wsim[base+512] = lb;
        g_Wsim[base+1024] = hb;
        wv = W_tau_w[i];
        hb = __float2bfloat16_rn(wv);
        hv = __bfloat162float(hb);
        lb = __float2bfloat16_rn(wv - hv);
        g_Wstau[base] = hb;
        g_Wstau[base+512] = lb;
        g_Wstau[base+1024] = hb;
    }
    for (int i = gtid; i < HH*IND; i += NTOT) {
        int rr = i >> 8;
        int cc = i & 255;
        int base = rr*768 + cc;
        float wv = U_w[i];
        __nv_bfloat16 hb = __float2bfloat16_rn(wv);
        float hv = __bfloat162float(hb);
        __nv_bfloat16 lb = __float2bfloat16_rn(wv - hv);
        g_Us[base] = hb;
        g_Us[base+256] = lb;
        g_Us[base+512] = hb;
    }
    for (size_t i = gtid; i < (size_t)TT*BB*IND; i += NTOT) {
        size_t rr = i >> 8;
        int cc = (int)(i & 255);
        float wv = x[i];
        __nv_bfloat16 hb = __float2bfloat16_rn(wv);
        float hv = __bfloat162float(hb);
        __nv_bfloat16 lb = __float2bfloat16_rn(wv - hv);
        g_Xs[rr*512 + cc] = hb;
        g_Xs[rr*512 + 256 + cc] = lb;
    }
    {
        __nv_bfloat16 mh = __float2bfloat16_rn(1e-6f);
        float mhv = __bfloat162float(mh);
        __nv_bfloat16 ml = __float2bfloat16_rn(1e-6f - mhv);
        __nv_bfloat16 zb = __float2bfloat16_rn(0.0f);
        for (int i = gtid; i < BB*HH; i += NTOT) {
            int rr = i >> 9;
            int cc = i & 511;
            g_zre[i] = 0.0f;
            g_zim[i] = 0.0f;
            g_Are[rr*1024+cc] = zb;
            g_Are[rr*1024+512+cc] = zb;
            g_Aim[rr*1024+cc] = zb;
            g_Aim[rr*1024+512+cc] = zb;
            g_Amod[rr*1024+cc] = mh;
            g_Amod[rr*1024+512+cc] = ml;
        }
    }
    for (int i = gtid; i < HH; i += NTOT) {
        g_bias_re[i] = W_real_b[i] + U_b[i] + b_real[i];
        g_bias_im[i] = W_imag_b[i] + U_b[i] + b_imag[i];
    }
    grid_barrier();

    // ---------------- per-block GEMM tile mapping ------------------------
    int which = bx >> 5;
    int tile  = bx & 31;
    int m0    = (tile >> 3) << 6;
    int n0    = (tile & 7)  << 6;

    const __nv_bfloat16* Abase;
    const __nv_bfloat16* Wg;
    float* C;
    int KP;
    int RSA;
    int RSW;
    if (which == 0) {
        Abase = g_Are;  Wg = g_Wsre;  C = g_gre;  KP = 1536; RSA = 1024; RSW = 1536;
    } else if (which == 1) {
        Abase = g_Aim;  Wg = g_Wsim;  C = g_gim;  KP = 1536; RSA = 1024; RSW = 1536;
    } else if (which == 2) {
        Abase = g_Amod; Wg = g_Wstau; C = g_gtau; KP = 1536; RSA = 1024; RSW = 1536;
    } else {
        Abase = g_Xs;   Wg = g_Us;    C = g_gux;  KP = 768;  RSA = 512;  RSW = 768;
    }
    int NC = KP >> 6;

    int lr  = tid >> 3;            // 0..63, one loader row per 8 threads
    int lc8 = (tid & 7) * 8;
    int wid = tid >> 5;            // 0..15
    int wm  = wid & 3;             // 16-row group
    int wn  = wid >> 2;            // 16-col group

    for (int t = 0; t < TT; t++) {
        // ================= phase A: split-bf16 wmma GEMM ===================
        {
            const __nv_bfloat16* Ag = Abase;
            if (which == 3) {
                Ag = g_Xs + (size_t)t*BB*512;
            }

            wmma::fragment<wmma::accumulator, 16, 16, 16, float> acc;
            wmma::fill_fragment(acc, 0.0f);

            uint4 ra = *(const uint4*)(Ag + (size_t)(m0+lr)*RSA + lc8);
            uint4 rb = *(const uint4*)(Wg + (size_t)(n0+lr)*RSW + lc8);
            *(uint4*)(&sA[0][lr*72 + lc8]) = ra;
            *(uint4*)(&sB[0][lr*72 + lc8]) = rb;
            __syncthreads();

            for (int ch = 0; ch < NC; ch++) {
                int cur = ch & 1;
                if (ch + 1 < NC) {
                    int kc = (ch + 1) << 6;
                    int ac;
                    if (which == 3) {
                        if (kc < 512) { ac = kc & 255; } else { ac = kc - 256; }
                    } else {
                        if (kc < 1024) { ac = kc & 511; } else { ac = kc - 512; }
                    }
                    ra = *(const uint4*)(Ag + (size_t)(m0+lr)*RSA + ac + lc8);
                    rb = *(const uint4*)(Wg + (size_t)(n0+lr)*RSW + kc + lc8);
                }
                const __nv_bfloat16* sAc = &sA[cur][0];
                const __nv_bfloat16* sBc = &sB[cur][0];
                #pragma unroll
                for (int q = 0; q < 4; q++) {
                    wmma::fragment<wmma::matrix_a, 16, 16, 16, __nv_bfloat16, wmma::row_major> fa;
                    wmma::fragment<wmma::matrix_b, 16, 16, 16, __nv_bfloat16, wmma::col_major> fb;
                    wmma::load_matrix_sync(fa, sAc + (wm*16)*72 + q*16, 72);
                    wmma::load_matrix_sync(fb, sBc + (wn*16)*72 + q*16, 72);
                    wmma::mma_sync(acc, fa, fb, acc);
                }
                if (ch + 1 < NC) {
                    int nxt = cur ^ 1;
                    *(uint4*)(&sA[nxt][lr*72 + lc8]) = ra;
                    *(uint4*)(&sB[nxt][lr*72 + lc8]) = rb;
                    __syncthreads();
                }
            }

            float* Cout = C + (size_t)(m0 + wm*16)*512 + n0 + wn*16;
            wmma::store_matrix_sync(Cout, acc, 512, wmma::mem_row_major);
        }
        grid_barrier();

        // ================= phase B1: elementwise + partial sums =============
        float dre[2];
        float dimm[2];
        float zreL[2];
        float zimL[2];
        {
            int i2 = bx * 512 + tid;
            float2 vre = ((const float2*)g_gre)[i2];
            float2 vim = ((const float2*)g_gim)[i2];
            float2 vta = ((const float2*)g_gtau)[i2];
            float2 vux = ((const float2*)g_gux)[i2];
            float2 vzr = ((const float2*)g_zre)[i2];
            float2 vzi = ((const float2*)g_zim)[i2];
            int h0 = (i2 & 255) * 2;
            float2 vbr  = *(const float2*)(&g_bias_re[h0]);
            float2 vbi  = *(const float2*)(&g_bias_im[h0]);
            float2 vwtb = *(const float2*)(&W_tau_b[h0]);
            float2 vtb  = *(const float2*)(&tau_bias[h0]);

            float tre[2];
            float tim[2];
            float tta[2];
            float tux[2];
            float tzr[2];
            float tzi[2];
            float tbr[2];
            float tbi[2];
            float twtb[2];
            float ttb[2];
            tre[0] = vre.x; tre[1] = vre.y;
            tim[0] = vim.x; tim[1] = vim.y;
            tta[0] = vta.x; tta[1] = vta.y;
            tux[0] = vux.x; tux[1] = vux.y;
            tzr[0] = vzr.x; tzr[1] = vzr.y;
            tzi[0] = vzi.x; tzi[1] = vzi.y;
            tbr[0] = vbr.x; tbr[1] = vbr.y;
            tbi[0] = vbi.x; tbi[1] = vbi.y;
            twtb[0] = vwtb.x; twtb[1] = vwtb.y;
            ttb[0] = vtb.x; ttb[1] = vtb.y;

            float lsum = 0.0f;
            #pragma unroll
            for (int j = 0; j < 2; j++) {
                float dzr = tre[j] + tux[j] + tbr[j] - tzr[j];
                float dzi = tim[j] + tux[j] + tbi[j] - tzi[j];
                float tau = clampf(sigf(tta[j] + twtb[j]) + ttb[j], 0.01f, 1.0f) + 1e-6f;
                float dr  = clampf(dzr / tau, -10.0f, 10.0f);
                float di  = clampf(dzi / tau, -10.0f, 10.0f);
                lsum += sqrtf(dr*dr + di*di + 1e-12f);
                dre[j] = dr;
                dimm[j] = di;
                zreL[j] = tzr[j];
                zimL[j] = tzi[j];
            }
            #pragma unroll
            for (int off = 16; off > 0; off >>= 1) {
                lsum += __shfl_down_sync(0xFFFFFFFFu, lsum, off);
            }
            if ((tid & 31) == 0) {
                rbuf[tid >> 5] = lsum;
            }
            __syncthreads();
            if (tid == 0) {
                float s = 0.0f;
                #pragma unroll
                for (int ww = 0; ww < 16; ww++) {
                    s += rbuf[ww];
                }
                g_partials[bx] = s;
            }
        }
        grid_barrier();

        // ================= phase B2: scale + update + readout ===============
        {
            if (tid < 128) {
                float pv = g_partials[tid];
                #pragma unroll
                for (int off = 16; off > 0; off >>= 1) {
                    pv += __shfl_down_sync(0xFFFFFFFFu, pv, off);
                }
                if ((tid & 31) == 0) {
                    warp_s[tid >> 5] = pv;
                }
            }
            __syncthreads();
            float tot  = ((warp_s[0] + warp_s[1]) + warp_s[2]) + warp_s[3];
            float mean = tot / (float)(BB * HH);
            float scale = 1.0f;
            if (mean > 5.0f) {
                scale = 5.0f / (mean + 1e-6f);
            }

            int i2 = bx * 512 + tid;
            int flat0 = i2 * 2;
            int arw   = flat0 >> 9;
            int acl   = flat0 & 511;
            int abase = arw*1024 + acl;

            float zrA[2];
            float ziA[2];
            #pragma unroll
            for (int j = 0; j < 2; j++) {
                float znr = clampf(zreL[j] + 0.1f * scale * dre[j],  -100.0f, 100.0f);
                float zni = clampf(zimL[j] + 0.1f * scale * dimm[j], -100.0f, 100.0f);
                zrA[j] = znr;
                ziA[j] = zni;
                float arv = tanhf(znr);
                float aiv = tanhf(zni);
                float amv = sqrtf(znr*znr + zni*zni + 1e-12f);
                __nv_bfloat16 hb;
                float hv;
                hb = __float2bfloat16_rn(arv);
                hv = __bfloat162float(hb);
                g_Are[abase+j] = hb;
                g_Are[abase+512+j] = __float2bfloat16_rn(arv - hv);
                hb = __float2bfloat16_rn(aiv);
                hv = __bfloat162float(hb);
                g_Aim[abase+j] = hb;
                g_Aim[abase+512+j] = __float2bfloat16_rn(aiv - hv);
                hb = __float2bfloat16_rn(amv);
                hv = __bfloat162float(hb);
                g_Amod[abase+j] = hb;
                g_Amod[abase+512+j] = __float2bfloat16_rn(amv - hv);
            }
            float2 vout;
            vout.x = zrA[0];
            vout.y = zrA[1];
            ((float2*)g_zre)[i2] = vout;
            ((float2*)(&zsm[0][0]))[tid] = vout;
            float2 vout2;
            vout2.x = ziA[0];
            vout2.y = ziA[1];
            ((float2*)g_zim)[i2] = vout2;
            __syncthreads();

            // readout: y[t, 2bx + r, :] = zsm[r] times out_w transpose + out_b
            int o   = tid & 63;
            int seg = tid >> 6;     // 0..7, each covers 64 k values
            float acc0 = 0.0f;
            float acc1 = 0.0f;
            const float4* wrow = (const float4*)(out_w + (size_t)o * 512 + seg * 64);
            #pragma unroll 16
            for (int k4 = 0; k4 < 16; k4++) {
                float4 wv = wrow[k4];
                float4 z0 = *(const float4*)(&zsm[0][seg*64 + k4*4]);
                float4 z1 = *(const float4*)(&zsm[1][seg*64 + k4*4]);
                acc0 += wv.x*z0.x + wv.y*z0.y + wv.z*z0.z + wv.w*z0.w;
                acc1 += wv.x*z1.x + wv.y*z1.y + wv.z*z1.z + wv.w*z1.w;
            }
            red[seg][0][o] = acc0;
            red[seg][1][o] = acc1;
            __syncthreads();
            if (seg == 0) {
                float ob = out_b[o];
                #pragma unroll
                for (int r = 0; r < 2; r++) {
                    float yv = ob;
                    #pragma unroll
                    for (int s = 0; s < 8; s++) {
                        yv += red[s][r][o];
                    }
                    y[((size_t)t * BB + bx*2 + r) * OUTD + o] = yv;
                }
            }
        }
        grid_barrier();
    }
}

// ---------------- host launcher (graph-capturable, single node) ------------
extern "C" void kernel_launch(void* const* d_in, const int* in_sizes, int n_in,
                              void* d_out, int out_size)
{
    const float* x         = (const float*)d_in[0];
    const float* W_real_w  = (const float*)d_in[1];
    const float* W_real_b  = (const float*)d_in[2];
    const float* W_imag_w  = (const float*)d_in[3];
    const float* W_imag_b  = (const float*)d_in[4];
    const float* U_w       = (const float*)d_in[5];
    const float* U_b       = (const float*)d_in[6];
    const float* W_tau_w   = (const float*)d_in[7];
    const float* W_tau_b   = (const float*)d_in[8];
    const float* mask_real = (const float*)d_in[9];
    const float* mask_imag = (const float*)d_in[10];
    const float* tau_bias  = (const float*)d_in[11];
    const float* b_real    = (const float*)d_in[12];
    const float* b_imag    = (const float*)d_in[13];
    const float* out_w     = (const float*)d_in[14];
    const float* out_b     = (const float*)d_in[15];
    float* y = (float*)d_out;

    twistor_persistent<<<NBLK, NTHR>>>(x, W_real_w, W_real_b, W_imag_w, W_imag_b,
                                       U_w, U_b, W_tau_w, W_tau_b,
                                       mask_real, mask_imag, tau_bias,
                                       b_real, b_imag, out_w, out_b, y);
}